// round 14
// baseline (speedup 1.0000x reference)
#include <cuda_runtime.h>
#include <cuda_bf16.h>
#include <cstdint>

// ChannelPolyLayer: out[b,o,x,y] = sum_c coeffs[b,o,c] * prod_v img[b,v,x,y]^powers[c,v]
// DEGREE=3, NUM_VARS=3, NUM_OUT=3, NUM_COEFFS=20, BATCH=16, H=W=512.
//
// Monomial order from _generate_powers(3,3):
//  0:1  1:v0  2:v1  3:v2  4:v0^2  5:v0v1  6:v0v2  7:v1^2  8:v1v2  9:v2^2
// 10:v0^3 11:v0^2v1 12:v0^2v2 13:v0v1^2 14:v0v1v2 15:v0v2^2
// 16:v1^3 17:v1^2v2 18:v1v2^2 19:v2^3
//
// Nested Horner, packed fma.rn.f32x2.
// R14 = R11 champion (persistent one-wave, batch/blockIdx.y, continuous
// MLP=6 register prefetch) with the STORE PATH offloaded to TMA:
// STG.128 (12 cyc issue each, ~4.4us/SM of LSU busy — the largest removable
// term in the measured L1=41%) is replaced by STS.128 into a 24KB smem
// staging buffer + 6x cp.async.bulk (4KB, shared->global, bulk_group) issued
// by thread 0. wait_group 0 at next loop-top lets each copy overlap the
// following iteration's loads+compute. Loop trip count is block-uniform,
// so in-loop barriers are safe.

#define HW_PIX (512 * 512)
#define PLANE4 (HW_PIX / 4)       // 65536 float4s per channel plane
#define HALF4  (PLANE4 / 2)       // 32768 items; item j covers float4 j, j+HALF4
#define NBATCH 16
#define NCOEF  20
#define TPB    256
#define CTAS_X 18                 // 18*16 = 288 CTAs ~= one wave at 2 CTAs/SM
#define STRIDE (CTAS_X * TPB)     // 4608
#define TILE_BYTES (TPB * 16)     // 4096 per staged tile

typedef unsigned long long ull;

__device__ __forceinline__ ull ffma2(ull a, ull b, ull c) {
    ull d;
    asm("fma.rn.f32x2 %0, %1, %2, %3;" : "=l"(d) : "l"(a), "l"(b), "l"(c));
    return d;
}

// Horner over a packed pair of pixels. c[] are {coeff,coeff} splat pairs.
__device__ __forceinline__ ull horner2(ull v0, ull v1, ull v2,
                                       const ull* __restrict__ c) {
    ull pA = ffma2(c[16], v1, c[7]);
    pA = ffma2(v1, pA, c[2]);
    pA = ffma2(v1, pA, c[0]);
    ull pB = ffma2(c[17], v1, c[8]);
    pB = ffma2(v1, pB, c[3]);
    ull pC = ffma2(c[18], v1, c[9]);
    ull C0 = ffma2(c[19], v2, pC);
    C0 = ffma2(C0, v2, pB);
    C0 = ffma2(C0, v2, pA);
    ull qA = ffma2(c[13], v1, c[5]);
    qA = ffma2(v1, qA, c[1]);
    ull qB = ffma2(c[14], v1, c[6]);
    ull C1 = ffma2(c[15], v2, qB);
    C1 = ffma2(C1, v2, qA);
    ull C2 = ffma2(c[11], v1, c[4]);
    C2 = ffma2(c[12], v2, C2);
    ull r = ffma2(c[10], v0, C2);
    r = ffma2(r, v0, C1);
    r = ffma2(r, v0, C0);
    return r;
}

__device__ __forceinline__ void bulk_store(const void* gdst, uint32_t ssrc,
                                           uint32_t bytes) {
    asm volatile(
        "cp.async.bulk.global.shared::cta.bulk_group [%0], [%1], %2;"
        :: "l"(gdst), "r"(ssrc), "r"(bytes) : "memory");
}
#define BULK_COMMIT() asm volatile("cp.async.bulk.commit_group;" ::: "memory")
#define BULK_WAIT0()  asm volatile("cp.async.bulk.wait_group 0;" ::: "memory")
#define FENCE_ASYNC() asm volatile("fence.proxy.async.shared::cta;" ::: "memory")

__global__ __launch_bounds__(TPB, 2) void channel_poly_kernel(
    const float* __restrict__ img,     // (B, 3, H, W)
    const float* __restrict__ coeffs,  // (B, 3, 20)
    float* __restrict__ out)           // (B, 3, H, W)
{
    __shared__ ulonglong2 obuf[6][TPB];   // 24 KB staging: [oc*2 + item][t]
    __shared__ ull sc2[3 * NCOEF];        // this batch's 60 splat pairs

    const int b = blockIdx.y;
    const int t = threadIdx.x;
    if (t < 3 * NCOEF) {
        ull u = (ull)__float_as_uint(coeffs[b * (3 * NCOEF) + t]);
        sc2[t] = u | (u << 32);        // splat {c, c}
    }
    __syncthreads();

    const ulonglong2* __restrict__ in =
        reinterpret_cast<const ulonglong2*>(img + (size_t)b * 3 * HW_PIX);
    ulonglong2* __restrict__ op =
        reinterpret_cast<ulonglong2*>(out + (size_t)b * 3 * HW_PIX);

    const uint32_t sbuf0 = (uint32_t)__cvta_generic_to_shared(&obuf[0][0]);

    int ibase = blockIdx.x * TPB;      // block-uniform item base (< 4608)
    int i = ibase + t;

    // Prefetch first item (6 LDG.128).
    ulonglong2 a0 = in[i],         a1 = in[i + PLANE4],
               a2 = in[i + 2 * PLANE4];
    ulonglong2 b0 = in[i + HALF4], b1 = in[i + HALF4 + PLANE4],
               b2 = in[i + HALF4 + 2 * PLANE4];

#pragma unroll 1
    while (ibase < HALF4) {            // uniform: HALF4, STRIDE, TPB aligned
        // Issue next item's 6 loads first (continuous MLP=6).
        const int nbase = ibase + STRIDE;
        const int il = (nbase < HALF4) ? i + STRIDE : i;  // safe addr on tail
        const ulonglong2 na0 = in[il],         na1 = in[il + PLANE4],
                         na2 = in[il + 2 * PLANE4];
        const ulonglong2 nb0 = in[il + HALF4], nb1 = in[il + HALF4 + PLANE4],
                         nb2 = in[il + HALF4 + 2 * PLANE4];

        // Reclaim staging buffer (previous iteration's bulk copies done).
        if (t == 0) BULK_WAIT0();
        __syncthreads();

#pragma unroll 1
        for (int oc = 0; oc < 3; oc++) {
            const ull* __restrict__ c = sc2 + oc * NCOEF;
            ulonglong2 ra, rb;
            ra.x = horner2(a0.x, a1.x, a2.x, c);
            ra.y = horner2(a0.y, a1.y, a2.y, c);
            rb.x = horner2(b0.x, b1.x, b2.x, c);
            rb.y = horner2(b0.y, b1.y, b2.y, c);
            obuf[oc * 2 + 0][t] = ra;      // STS.128 (crossbar, cheap)
            obuf[oc * 2 + 1][t] = rb;
        }
        __syncthreads();

        // One thread drains the 6 staged 4KB tiles via TMA bulk stores.
        if (t == 0) {
            FENCE_ASYNC();
#pragma unroll
            for (int oc = 0; oc < 3; oc++) {
                bulk_store(op + (size_t)oc * PLANE4 + ibase,
                           sbuf0 + (oc * 2 + 0) * TILE_BYTES, TILE_BYTES);
                bulk_store(op + (size_t)oc * PLANE4 + HALF4 + ibase,
                           sbuf0 + (oc * 2 + 1) * TILE_BYTES, TILE_BYTES);
            }
            BULK_COMMIT();
        }

        // Rotate pipeline.
        ibase = nbase; i += STRIDE;
        a0 = na0; a1 = na1; a2 = na2;
        b0 = nb0; b1 = nb1; b2 = nb2;
    }

    // Ensure the final bulk group lands before the CTA exits.
    if (t == 0) BULK_WAIT0();
}

extern "C" void kernel_launch(void* const* d_in, const int* in_sizes, int n_in,
                              void* d_out, int out_size) {
    const float* img = (const float*)d_in[0];     // (16,3,512,512)
    const float* coeffs = (const float*)d_in[1];  // (16,3,20)
    float* out = (float*)d_out;

    dim3 grid(CTAS_X, NBATCH, 1);                 // 18 x 16 = 288 CTAs
    channel_poly_kernel<<<grid, TPB>>>(img, coeffs, out);
}

// round 15
// speedup vs baseline: 1.2133x; 1.2133x over previous
#include <cuda_runtime.h>
#include <cuda_bf16.h>

// ChannelPolyLayer: out[b,o,x,y] = sum_c coeffs[b,o,c] * prod_v img[b,v,x,y]^powers[c,v]
// DEGREE=3, NUM_VARS=3, NUM_OUT=3, NUM_COEFFS=20, BATCH=16, H=W=512.
//
// Monomial order from _generate_powers(3,3):
//  0:1  1:v0  2:v1  3:v2  4:v0^2  5:v0v1  6:v0v2  7:v1^2  8:v1v2  9:v2^2
// 10:v0^3 11:v0^2v1 12:v0^2v2 13:v0v1^2 14:v0v1v2 15:v0v2^2
// 16:v1^3 17:v1^2v2 18:v1v2^2 19:v2^3
//
// Nested Horner, packed fma.rn.f32x2 (19 per output per pixel-pair).
// R15 combines the two independently-measured winners:
//  - R8's per-iteration body (BEST ncu-dur 16.4us): 4 float4 items/thread,
//    all 12 LDG.128 front-batched, TPB=128, batch = blockIdx.y.
//  - R11's launch shape (BEST wall overhead ~ -0.2us): persistent ~one-wave
//    grid, 46x16 = 736 CTAs at 5 CTAs/SM, grid-stride loop (2-3 iters/CTA).
// No per-iteration barriers (R14 lesson). launch_bounds(128,5) = 102-reg
// cap >= R8's measured 94 (no R5-style squeeze).

#define HW_PIX (512 * 512)
#define PLANE4 (HW_PIX / 4)       // 65536 float4s per channel plane
#define QUART  (PLANE4 / 4)       // 16384: item j lives at i + j*QUART
#define NBATCH 16
#define NCOEF  20
#define TPB    128
#define NTILE  (QUART / TPB)      // 128 tiles of 128 threads per batch
#define CTAS_X 46                 // 46*16 = 736 CTAs ~= one wave at 5 CTAs/SM

typedef unsigned long long ull;

__device__ __forceinline__ ull ffma2(ull a, ull b, ull c) {
    ull d;
    asm("fma.rn.f32x2 %0, %1, %2, %3;" : "=l"(d) : "l"(a), "l"(b), "l"(c));
    return d;
}

// Horner over a packed pair of pixels. c[] are {coeff,coeff} splat pairs.
__device__ __forceinline__ ull horner2(ull v0, ull v1, ull v2,
                                       const ull* __restrict__ c) {
    ull pA = ffma2(c[16], v1, c[7]);
    pA = ffma2(v1, pA, c[2]);
    pA = ffma2(v1, pA, c[0]);
    ull pB = ffma2(c[17], v1, c[8]);
    pB = ffma2(v1, pB, c[3]);
    ull pC = ffma2(c[18], v1, c[9]);
    ull C0 = ffma2(c[19], v2, pC);
    C0 = ffma2(C0, v2, pB);
    C0 = ffma2(C0, v2, pA);
    ull qA = ffma2(c[13], v1, c[5]);
    qA = ffma2(v1, qA, c[1]);
    ull qB = ffma2(c[14], v1, c[6]);
    ull C1 = ffma2(c[15], v2, qB);
    C1 = ffma2(C1, v2, qA);
    ull C2 = ffma2(c[11], v1, c[4]);
    C2 = ffma2(c[12], v2, C2);
    ull r = ffma2(c[10], v0, C2);
    r = ffma2(r, v0, C1);
    r = ffma2(r, v0, C0);
    return r;
}

__global__ __launch_bounds__(TPB, 5) void channel_poly_kernel(
    const float* __restrict__ img,     // (B, 3, H, W)
    const float* __restrict__ coeffs,  // (B, 3, 20)
    float* __restrict__ out)           // (B, 3, H, W)
{
    __shared__ ull sc2[3 * NCOEF];     // this batch's 60 splat pairs
    const int b = blockIdx.y;
    const int t = threadIdx.x;
    if (t < 3 * NCOEF) {
        ull u = (ull)__float_as_uint(coeffs[b * (3 * NCOEF) + t]);
        sc2[t] = u | (u << 32);        // splat {c, c}
    }
    __syncthreads();                   // once per CTA, before the loop

    const ulonglong2* __restrict__ in =
        reinterpret_cast<const ulonglong2*>(img + (size_t)b * 3 * HW_PIX);
    ulonglong2* __restrict__ op =
        reinterpret_cast<ulonglong2*>(out + (size_t)b * 3 * HW_PIX);

#pragma unroll 1
    for (int k = blockIdx.x; k < NTILE; k += CTAS_X) {
        const int i = k * TPB + t;     // 0..16383

        // R8 body: front-batch all 12 LDG.128 (MLP_p1 = 12).
        const ulonglong2 a0 = in[i];
        const ulonglong2 a1 = in[i + PLANE4];
        const ulonglong2 a2 = in[i + 2 * PLANE4];
        const ulonglong2 b0 = in[i + QUART];
        const ulonglong2 b1 = in[i + QUART + PLANE4];
        const ulonglong2 b2 = in[i + QUART + 2 * PLANE4];
        const ulonglong2 c0 = in[i + 2 * QUART];
        const ulonglong2 c1 = in[i + 2 * QUART + PLANE4];
        const ulonglong2 c2 = in[i + 2 * QUART + 2 * PLANE4];
        const ulonglong2 d0 = in[i + 3 * QUART];
        const ulonglong2 d1 = in[i + 3 * QUART + PLANE4];
        const ulonglong2 d2 = in[i + 3 * QUART + 2 * PLANE4];

#pragma unroll 1
        for (int oc = 0; oc < 3; oc++) {
            const ull* __restrict__ c = sc2 + oc * NCOEF;
            ulonglong2 ra, rb, rc, rd;
            ra.x = horner2(a0.x, a1.x, a2.x, c);
            ra.y = horner2(a0.y, a1.y, a2.y, c);
            rb.x = horner2(b0.x, b1.x, b2.x, c);
            rb.y = horner2(b0.y, b1.y, b2.y, c);
            rc.x = horner2(c0.x, c1.x, c2.x, c);
            rc.y = horner2(c0.y, c1.y, c2.y, c);
            rd.x = horner2(d0.x, d1.x, d2.x, c);
            rd.y = horner2(d0.y, d1.y, d2.y, c);
            op[i + oc * PLANE4] = ra;
            op[i + QUART + oc * PLANE4] = rb;
            op[i + 2 * QUART + oc * PLANE4] = rc;
            op[i + 3 * QUART + oc * PLANE4] = rd;
        }
    }
}

extern "C" void kernel_launch(void* const* d_in, const int* in_sizes, int n_in,
                              void* d_out, int out_size) {
    const float* img = (const float*)d_in[0];     // (16,3,512,512)
    const float* coeffs = (const float*)d_in[1];  // (16,3,20)
    float* out = (float*)d_out;

    dim3 grid(CTAS_X, NBATCH, 1);                 // 46 x 16 = 736 CTAs
    channel_poly_kernel<<<grid, TPB>>>(img, coeffs, out);
}

// round 16
// speedup vs baseline: 1.2381x; 1.0204x over previous
#include <cuda_runtime.h>
#include <cuda_bf16.h>

// ChannelPolyLayer: out[b,o,x,y] = sum_c coeffs[b,o,c] * prod_v img[b,v,x,y]^powers[c,v]
// DEGREE=3, NUM_VARS=3, NUM_OUT=3, NUM_COEFFS=20, BATCH=16, H=W=512.
//
// Monomial order from _generate_powers(3,3):
//  0:1  1:v0  2:v1  3:v2  4:v0^2  5:v0v1  6:v0v2  7:v1^2  8:v1v2  9:v2^2
// 10:v0^3 11:v0^2v1 12:v0^2v2 13:v0v1^2 14:v0v1v2 15:v0v2^2
// 16:v1^3 17:v1^2v2 18:v1v2^2 19:v2^3
//
// Nested Horner, packed fma.rn.f32x2 (19 per output per pixel-pair).
// R16 = champion R11 (persistent one-wave, batch/blockIdx.y, continuous
// MLP=6 register prefetch) with CTAS_X=16 so STRIDE=4096 divides
// HALF4=32768 exactly: every thread runs exactly 8 iterations. The loop is
// peeled into 7 pipelined iterations + 1 bare final compute, removing the
// per-iteration clamp select, bound compare, and the tail's duplicate
// prefetch burst. Strictly-local change to the best measured kernel.

#define HW_PIX (512 * 512)
#define PLANE4 (HW_PIX / 4)       // 65536 float4s per channel plane
#define HALF4  (PLANE4 / 2)       // 32768 items; item j covers float4 j, j+HALF4
#define NBATCH 16
#define NCOEF  20
#define TPB    256
#define CTAS_X 16                 // 16*16 = 256 CTAs, one wave at 2 CTAs/SM
#define STRIDE (CTAS_X * TPB)     // 4096 -> HALF4/STRIDE = 8 exact iterations

typedef unsigned long long ull;

__device__ __forceinline__ ull ffma2(ull a, ull b, ull c) {
    ull d;
    asm("fma.rn.f32x2 %0, %1, %2, %3;" : "=l"(d) : "l"(a), "l"(b), "l"(c));
    return d;
}

// Horner over a packed pair of pixels. c[] are {coeff,coeff} splat pairs.
__device__ __forceinline__ ull horner2(ull v0, ull v1, ull v2,
                                       const ull* __restrict__ c) {
    ull pA = ffma2(c[16], v1, c[7]);
    pA = ffma2(v1, pA, c[2]);
    pA = ffma2(v1, pA, c[0]);
    ull pB = ffma2(c[17], v1, c[8]);
    pB = ffma2(v1, pB, c[3]);
    ull pC = ffma2(c[18], v1, c[9]);
    ull C0 = ffma2(c[19], v2, pC);
    C0 = ffma2(C0, v2, pB);
    C0 = ffma2(C0, v2, pA);
    ull qA = ffma2(c[13], v1, c[5]);
    qA = ffma2(v1, qA, c[1]);
    ull qB = ffma2(c[14], v1, c[6]);
    ull C1 = ffma2(c[15], v2, qB);
    C1 = ffma2(C1, v2, qA);
    ull C2 = ffma2(c[11], v1, c[4]);
    C2 = ffma2(c[12], v2, C2);
    ull r = ffma2(c[10], v0, C2);
    r = ffma2(r, v0, C1);
    r = ffma2(r, v0, C0);
    return r;
}

__global__ __launch_bounds__(TPB, 2) void channel_poly_kernel(
    const float* __restrict__ img,     // (B, 3, H, W)
    const float* __restrict__ coeffs,  // (B, 3, 20)
    float* __restrict__ out)           // (B, 3, H, W)
{
    __shared__ ull sc2[3 * NCOEF];     // this batch's 60 splat pairs
    const int b = blockIdx.y;
    const int t = threadIdx.x;
    if (t < 3 * NCOEF) {
        ull u = (ull)__float_as_uint(coeffs[b * (3 * NCOEF) + t]);
        sc2[t] = u | (u << 32);        // splat {c, c}
    }
    __syncthreads();                   // the only barrier

    const ulonglong2* __restrict__ in =
        reinterpret_cast<const ulonglong2*>(img + (size_t)b * 3 * HW_PIX);
    ulonglong2* __restrict__ op =
        reinterpret_cast<ulonglong2*>(out + (size_t)b * 3 * HW_PIX);

    int i = blockIdx.x * TPB + t;      // < 4096

    // Prefetch first item (6 LDG.128).
    ulonglong2 a0 = in[i],         a1 = in[i + PLANE4],
               a2 = in[i + 2 * PLANE4];
    ulonglong2 b0 = in[i + HALF4], b1 = in[i + HALF4 + PLANE4],
               b2 = in[i + HALF4 + 2 * PLANE4];

    // 7 pipelined iterations: prefetch next, compute current. Exact trip
    // count (HALF4/STRIDE = 8) -> no clamp, no bound compare on loads.
#pragma unroll 1
    for (int it = 0; it < 7; it++) {
        const int inext = i + STRIDE;  // always in-bounds for iterations 0..6
        const ulonglong2 na0 = in[inext],         na1 = in[inext + PLANE4],
                         na2 = in[inext + 2 * PLANE4];
        const ulonglong2 nb0 = in[inext + HALF4], nb1 = in[inext + HALF4 + PLANE4],
                         nb2 = in[inext + HALF4 + 2 * PLANE4];

#pragma unroll 1
        for (int oc = 0; oc < 3; oc++) {
            const ull* __restrict__ c = sc2 + oc * NCOEF;
            ulonglong2 ra, rb;
            ra.x = horner2(a0.x, a1.x, a2.x, c);
            ra.y = horner2(a0.y, a1.y, a2.y, c);
            rb.x = horner2(b0.x, b1.x, b2.x, c);
            rb.y = horner2(b0.y, b1.y, b2.y, c);
            op[i + oc * PLANE4] = ra;
            op[i + HALF4 + oc * PLANE4] = rb;
        }

        i = inext;
        a0 = na0; a1 = na1; a2 = na2;
        b0 = nb0; b1 = nb1; b2 = nb2;
    }

    // Peeled final iteration: compute + store only, no prefetch.
#pragma unroll 1
    for (int oc = 0; oc < 3; oc++) {
        const ull* __restrict__ c = sc2 + oc * NCOEF;
        ulonglong2 ra, rb;
        ra.x = horner2(a0.x, a1.x, a2.x, c);
        ra.y = horner2(a0.y, a1.y, a2.y, c);
        rb.x = horner2(b0.x, b1.x, b2.x, c);
        rb.y = horner2(b0.y, b1.y, b2.y, c);
        op[i + oc * PLANE4] = ra;
        op[i + HALF4 + oc * PLANE4] = rb;
    }
}

extern "C" void kernel_launch(void* const* d_in, const int* in_sizes, int n_in,
                              void* d_out, int out_size) {
    const float* img = (const float*)d_in[0];     // (16,3,512,512)
    const float* coeffs = (const float*)d_in[1];  // (16,3,20)
    float* out = (float*)d_out;

    dim3 grid(CTAS_X, NBATCH, 1);                 // 16 x 16 = 256 CTAs
    channel_poly_kernel<<<grid, TPB>>>(img, coeffs, out);
}